// round 2
// baseline (speedup 1.0000x reference)
#include <cuda_runtime.h>

#define NB    500          // number of DVH points per batch
#define NH    501          // histogram buckets (searchsorted index 0..500)
#define BATCH 4
#define NPER  (128*128*128)  // elements per batch = 2,097,152
#define NVEC  (NPER/4)

// Global scratch (no allocations allowed) — zeroed each launch by zero_k.
__device__ int g_hist[BATCH][2][NH];   // [batch][0=pred,1=gt][bucket]
__device__ int g_mcount[BATCH];        // masked-voxel count per batch

__global__ void zero_k() {
    int i = blockIdx.x * blockDim.x + threadIdx.x;
    const int tot = BATCH * 2 * NH;
    if (i < tot) ((int*)g_hist)[i] = 0;
    if (i < BATCH) g_mcount[i] = 0;
}

__global__ __launch_bounds__(256) void hist_k(
    const float* __restrict__ dpred,
    const float* __restrict__ dgt,
    const float* __restrict__ msk)
{
    __shared__ int sh[2 * NH];
    __shared__ int smc;
    const int tid = threadIdx.x;
    for (int i = tid; i < 2 * NH; i += blockDim.x) sh[i] = 0;
    if (tid == 0) smc = 0;
    __syncthreads();

    const int b = blockIdx.y;
    const float4* __restrict__ p4 = (const float4*)(dpred + (size_t)b * NPER);
    const float4* __restrict__ g4 = (const float4*)(dgt   + (size_t)b * NPER);
    const float4* __restrict__ m4 = (const float4*)(msk   + (size_t)b * NPER);

    const float INVH = 499.0f / 75.0f;   // 1 / bin-spacing of linspace(0,75,500)
    int mc = 0;

    for (int i = blockIdx.x * blockDim.x + tid; i < NVEC; i += gridDim.x * blockDim.x) {
        float4 m = m4[i];
        float4 a = p4[i];
        float4 g = g4[i];
        float mm[4] = {m.x, m.y, m.z, m.w};
        float aa[4] = {a.x, a.y, a.z, a.w};
        float gg[4] = {g.x, g.y, g.z, g.w};
        #pragma unroll
        for (int j = 0; j < 4; j++) {
            if (mm[j] != 0.0f) {          // mask is exactly 0.0 or 1.0
                mc++;
                // searchsorted(bins, dose, 'right') for dose >= 0
                int cp = (int)(aa[j] * INVH) + 1;
                int cg = (int)(gg[j] * INVH) + 1;
                cp = min(cp, NB);         // fp safety: clamp to last bucket
                cg = min(cg, NB);
                atomicAdd(&sh[cp], 1);
                atomicAdd(&sh[NH + cg], 1);
            }
        }
    }

    atomicAdd(&smc, mc);
    __syncthreads();

    int* gh = &g_hist[b][0][0];
    for (int i = tid; i < 2 * NH; i += blockDim.x) {
        int v = sh[i];
        if (v) atomicAdd(&gh[i], v);       // RED (no return) — fire and forget
    }
    if (tid == 0 && smc) atomicAdd(&g_mcount[b], smc);
}

__global__ __launch_bounds__(512) void fin_k(float* __restrict__ out) {
    __shared__ float sh[512];
    const int tid = threadIdx.x;
    float acc = 0.0f;

    for (int b = 0; b < BATCH; b++) {
        float denom = (float)g_mcount[b] + 1e-6f;
        // d[i] = hist_pred[i] - hist_gt[i]; suffix sum gives count_ge difference
        float v = 0.0f;
        if (tid < NH) v = (float)(g_hist[b][0][tid] - g_hist[b][1][tid]);
        sh[tid] = v;
        __syncthreads();
        // Hillis-Steele inclusive SUFFIX scan: sh[i] = sum_{j>=i} d[j]
        #pragma unroll
        for (int off = 1; off < 512; off <<= 1) {
            float t = (tid + off < 512) ? sh[tid + off] : 0.0f;
            __syncthreads();
            sh[tid] += t;
            __syncthreads();
        }
        if (tid < NB) {
            float diff = sh[tid + 1] / denom;   // count_ge[k] needs c >= k+1
            acc += diff * diff;
        }
        __syncthreads();
    }

    // block reduction of acc
    sh[tid] = acc;
    __syncthreads();
    #pragma unroll
    for (int off = 256; off > 0; off >>= 1) {
        if (tid < off) sh[tid] += sh[tid + off];
        __syncthreads();
    }
    if (tid == 0) out[0] = sh[0] / (float)(BATCH * NB);
}

extern "C" void kernel_launch(void* const* d_in, const int* in_sizes, int n_in,
                              void* d_out, int out_size)
{
    const float* dpred = (const float*)d_in[0];
    const float* dgt   = (const float*)d_in[1];
    const float* msk   = (const float*)d_in[2];

    zero_k<<<(BATCH * 2 * NH + 255) / 256, 256>>>();

    dim3 grid(128, BATCH);   // 512 CTAs total -> ~3.4 resident CTAs/SM, single wave
    hist_k<<<grid, 256>>>(dpred, dgt, msk);

    fin_k<<<1, 512>>>((float*)d_out);
}

// round 3
// speedup vs baseline: 1.0880x; 1.0880x over previous
#include <cuda_runtime.h>

#define NB    500            // DVH points per batch
#define NH    501            // histogram buckets (searchsorted index 0..500)
#define BATCH 4
#define NPER  (128*128*128)  // 2,097,152 elements per batch
#define NVEC  (NPER/4)       // float4 count per batch = 524288
#define GX    256            // x-blocks per batch
#define TPB   256
// iterations per thread = NVEC / (GX*TPB) = 8 (exact)
#define ITERS (NVEC / (GX * TPB))

// Persistent scratch (zero-init at module load; fin_k re-zeroes after use,
// so every kernel_launch call sees clean state -> graph-replay safe).
__device__ int g_hist[BATCH][NH];   // difference histogram: pred - gt
__device__ int g_mcount[BATCH];     // masked-voxel count per batch

__global__ __launch_bounds__(TPB, 6) void hist_k(
    const float* __restrict__ dpred,
    const float* __restrict__ dgt,
    const float* __restrict__ msk)
{
    __shared__ int sh[NH];
    const int tid = threadIdx.x;
    for (int i = tid; i < NH; i += TPB) sh[i] = 0;
    __syncthreads();

    const int b = blockIdx.y;
    const float4* __restrict__ p4 = (const float4*)(dpred + (size_t)b * NPER);
    const float4* __restrict__ g4 = (const float4*)(dgt   + (size_t)b * NPER);
    const float4* __restrict__ m4 = (const float4*)(msk   + (size_t)b * NPER);

    const float INVH = 499.0f / 75.0f;   // 1/h for bins = linspace(0,75,500)
    const int base = blockIdx.x * TPB + tid;
    int mc = 0;

    #pragma unroll 2
    for (int j = 0; j < ITERS; j++) {
        const int i = base + j * (GX * TPB);
        float4 m = m4[i];
        float4 a = p4[i];
        float4 g = g4[i];
        float mm[4] = {m.x, m.y, m.z, m.w};
        float aa[4] = {a.x, a.y, a.z, a.w};
        float gg[4] = {g.x, g.y, g.z, g.w};
        #pragma unroll
        for (int e = 0; e < 4; e++) {
            if (mm[e] != 0.0f) {               // mask is exactly 0.0 or 1.0
                mc++;
                int cp = min((int)(aa[e] * INVH) + 1, NB);
                int cg = min((int)(gg[e] * INVH) + 1, NB);
                atomicAdd(&sh[cp],  1);        // diff histogram: +pred
                atomicAdd(&sh[cg], -1);        //                 -gt
            }
        }
    }

    // masked count: warp reduce, one global RED per warp
    #pragma unroll
    for (int off = 16; off > 0; off >>= 1)
        mc += __shfl_down_sync(0xffffffffu, mc, off);
    if ((tid & 31) == 0 && mc) atomicAdd(&g_mcount[b], mc);

    __syncthreads();
    for (int i = tid; i < NH; i += TPB) {
        int v = sh[i];
        if (v) atomicAdd(&g_hist[b][i], v);    // RED, fire-and-forget
    }
}

// One warp per batch; register-resident suffix scan; re-zeroes scratch.
__global__ __launch_bounds__(128) void fin_k(float* __restrict__ out) {
    __shared__ float warp_acc[4];
    const int tid  = threadIdx.x;
    const int wid  = tid >> 5;
    const int lane = tid & 31;
    const unsigned FULL = 0xffffffffu;

    if (wid < BATCH) {
        const int b = wid;
        const float denom = (float)g_mcount[b] + 1e-6f;

        // 16 chunks of 32: x[k] = diff-hist[32k + lane] (pad to 512)
        float s[16];
        #pragma unroll
        for (int k = 0; k < 16; k++) {
            int idx = k * 32 + lane;
            float v = (idx < NH) ? (float)g_hist[b][idx] : 0.0f;
            // inclusive suffix scan within chunk (shfl_down)
            #pragma unroll
            for (int off = 1; off < 32; off <<= 1) {
                float t = __shfl_down_sync(FULL, v, off);
                if (lane + off < 32) v += t;
            }
            s[k] = v;
        }
        // chunk totals = suffix value at lane 0
        float tails[16];
        float run = 0.0f;
        #pragma unroll
        for (int k = 15; k >= 0; k--) {
            tails[k] = run;
            run += __shfl_sync(FULL, s[k], 0);
        }
        // loss: DVH points use suffix at histogram index 1..500
        float acc = 0.0f;
        #pragma unroll
        for (int k = 0; k < 16; k++) {
            int idx = k * 32 + lane;
            if (idx >= 1 && idx <= NB) {
                float d = (s[k] + tails[k]) / denom;
                acc += d * d;
            }
        }
        #pragma unroll
        for (int off = 16; off > 0; off >>= 1)
            acc += __shfl_down_sync(FULL, acc, off);
        if (lane == 0) warp_acc[b] = acc;
    }
    __syncthreads();
    if (tid == 0)
        out[0] = (warp_acc[0] + warp_acc[1] + warp_acc[2] + warp_acc[3])
               / (float)(BATCH * NB);

    // self-clean for next replay (graph-capture safe, no extra kernel)
    for (int i = tid; i < BATCH * NH; i += 128) ((int*)g_hist)[i] = 0;
    if (tid < BATCH) g_mcount[tid] = 0;
}

extern "C" void kernel_launch(void* const* d_in, const int* in_sizes, int n_in,
                              void* d_out, int out_size)
{
    const float* dpred = (const float*)d_in[0];
    const float* dgt   = (const float*)d_in[1];
    const float* msk   = (const float*)d_in[2];

    dim3 grid(GX, BATCH);            // 1024 CTAs, ~6.9/SM
    hist_k<<<grid, TPB>>>(dpred, dgt, msk);
    fin_k<<<1, 128>>>((float*)d_out);
}